// round 2
// baseline (speedup 1.0000x reference)
#include <cuda_runtime.h>
#include <cuda_bf16.h>
#include <cstdint>

#define B_    32
#define T_    4096
#define D_    256
#define H_    256
#define G4_   1024
#define HOR_  24
#define GCTA  128

// ---------------- device scratch (static: no runtime allocation) ----------------
__device__ __align__(16) float g_XG[(size_t)T_ * G4_ * B_];   // [t][n][b], 512 MB
__device__ __align__(16) float g_h[2][B_ * H_];               // ping-pong hidden state [b][j]
__device__ unsigned int g_ctr;

// ---------------- helpers ----------------
typedef unsigned long long ull;

__device__ __forceinline__ ull pack2(float x, float y) {
    ull r;
    asm("mov.b64 %0, {%1, %2};" : "=l"(r) : "f"(x), "f"(y));
    return r;
}
__device__ __forceinline__ void unpack2(ull v, float& x, float& y) {
    asm("mov.b64 {%0, %1}, %2;" : "=f"(x), "=f"(y) : "l"(v));
}
// a += w * x (elementwise packed fp32x2)
__device__ __forceinline__ ull fma2(ull a, ull w, ull x) {
    asm("fma.rn.f32x2 %0, %1, %2, %0;" : "+l"(a) : "l"(w), "l"(x));
    return a;
}
__device__ __forceinline__ float sigf(float x) { return 1.f / (1.f + __expf(-x)); }

// ---------------- kernel 0: init state + barrier counter ----------------
__global__ void k_init() {
    int tid = threadIdx.x;
    for (int i = tid; i < B_ * H_; i += 256) g_h[0][i] = 0.f;
    if (tid == 0) g_ctr = 0u;
}

// ---------------- kernel 1: XG[t][n][b] = sum_k x[b][t][k]*W[k][n] + b_lstm[n] ----------------
// grid (T_, 16), 256 threads. Each CTA: one t, 64 n-columns.
__global__ void __launch_bounds__(256) k_xgemm(const float* __restrict__ x,
                                               const float* __restrict__ W,
                                               const float* __restrict__ bl) {
    __shared__ __align__(16) float xs[256][32];   // [k][b]
    __shared__ __align__(16) float ws[32][64];    // [kk][nn]
    int t  = blockIdx.x;
    int n0 = blockIdx.y * 64;
    int tid = threadIdx.x;
    int b  = tid & 31;
    int ng = tid >> 5;   // 0..7, 8 n-values per thread

    // load x_t [32 rows of 256] transposed into xs[k][b]
    {
        int br = tid >> 3;           // row 0..31
        int kq = (tid & 7) * 32;     // k offset
        const float4* src = (const float4*)(x + ((size_t)br * T_ + t) * D_ + kq);
        #pragma unroll
        for (int q = 0; q < 8; q++) {
            float4 v = src[q];
            int k = kq + q * 4;
            xs[k][br] = v.x; xs[k + 1][br] = v.y; xs[k + 2][br] = v.z; xs[k + 3][br] = v.w;
        }
    }

    ull acc[4];
    #pragma unroll
    for (int p = 0; p < 4; p++) acc[p] = 0ull;

    for (int kc = 0; kc < 8; kc++) {
        __syncthreads();
        // stage W chunk [32 k][64 n]
        for (int i = tid; i < 2048; i += 256) {
            int kk = i >> 6, nn = i & 63;
            ws[kk][nn] = W[(size_t)(kc * 32 + kk) * G4_ + n0 + nn];
        }
        __syncthreads();
        #pragma unroll
        for (int kk = 0; kk < 32; kk++) {
            float xv = xs[kc * 32 + kk][b];
            ull xx = pack2(xv, xv);
            float4 w0 = *(const float4*)&ws[kk][ng * 8];
            float4 w1 = *(const float4*)&ws[kk][ng * 8 + 4];
            acc[0] = fma2(acc[0], pack2(w0.x, w0.y), xx);
            acc[1] = fma2(acc[1], pack2(w0.z, w0.w), xx);
            acc[2] = fma2(acc[2], pack2(w1.x, w1.y), xx);
            acc[3] = fma2(acc[3], pack2(w1.z, w1.w), xx);
        }
    }

    size_t base = (size_t)t * (G4_ * B_) + (size_t)(n0 + ng * 8) * B_ + b;
    #pragma unroll
    for (int p = 0; p < 4; p++) {
        float ax, ay;
        unpack2(acc[p], ax, ay);
        int n = n0 + ng * 8 + 2 * p;
        g_XG[base + (size_t)(2 * p) * B_]     = ax + bl[n];
        g_XG[base + (size_t)(2 * p + 1) * B_] = ay + bl[n + 1];
    }
}

// ---------------- kernel 2: persistent LSTM recurrence ----------------
// 128 CTAs x 256 threads. CTA c owns hidden units {2c, 2c+1} -> 8 gate rows.
__global__ void __launch_bounds__(256, 1) k_rnn(const float* __restrict__ W) {
    __shared__ __align__(16) float Whs[8][256];       // [l][j] stationary weights
    __shared__ float partial[8][8][32];               // [l][jg][b]
    __shared__ float gates_s[8][32];                  // [l][b]
    __shared__ float cst[2][32];                      // cell state [which][b]

    int tid = threadIdx.x;
    int b   = tid & 31;
    int jg  = tid >> 5;          // 0..7 : K-split group  (also l for epilogue)
    int c2  = 2 * (int)blockIdx.x;

    // stationary Wh slice: Whs[l][j] = W[(256+j)*1024 + n(l)],  n(l) = (l>>1)*256 + c2 + (l&1)
    #pragma unroll
    for (int l = 0; l < 8; l++) {
        int n = ((l >> 1) << 8) + c2 + (l & 1);
        Whs[l][tid] = W[(size_t)(D_ + tid) * G4_ + n];
    }
    if (tid < 64) cst[tid >> 5][tid & 31] = 0.f;
    __syncthreads();

    int n_e = ((jg >> 1) << 8) + c2 + (jg & 1);   // epilogue gate row for (l=jg, b)

    for (int t = 0; t < T_; ++t) {
        // prefetch XG for this thread's epilogue output (independent of barrier)
        float xg = g_XG[(size_t)t * (G4_ * B_) + (size_t)n_e * B_ + b];

        // wait for h_t to be published by all CTAs
        if (tid == 0 && t > 0) {
            unsigned tgt = (unsigned)t * GCTA;
            unsigned v;
            do {
                asm volatile("ld.acquire.gpu.u32 %0, [%1];" : "=r"(v) : "l"(&g_ctr) : "memory");
            } while (v < tgt);
        }
        __syncthreads();

        // load h[b][jg*32 .. +32] (L2-only to avoid stale L1 across CTAs)
        const float4* hp = (const float4*)(&g_h[t & 1][b * H_ + jg * 32]);
        ull hreg[16];
        #pragma unroll
        for (int q = 0; q < 8; q++) {
            float4 v = __ldcg(hp + q);
            hreg[2 * q]     = pack2(v.x, v.y);
            hreg[2 * q + 1] = pack2(v.z, v.w);
        }

        // partial dot products: 8 gate rows x 32-wide K slice
        float accs[8];
        #pragma unroll
        for (int l = 0; l < 8; l++) {
            ull a = 0ull;
            const float4* wp = (const float4*)&Whs[l][jg * 32];
            #pragma unroll
            for (int q = 0; q < 8; q++) {
                float4 w = wp[q];
                a = fma2(a, pack2(w.x, w.y), hreg[2 * q]);
                a = fma2(a, pack2(w.z, w.w), hreg[2 * q + 1]);
            }
            float ax, ay;
            unpack2(a, ax, ay);
            accs[l] = ax + ay;
        }
        #pragma unroll
        for (int l = 0; l < 8; l++) partial[l][jg][b] = accs[l];
        __syncthreads();

        // reduce across K groups; thread (l=jg, b)
        float gsum = xg;
        #pragma unroll
        for (int q = 0; q < 8; q++) gsum += partial[jg][q][b];
        gates_s[jg][b] = gsum;
        __syncthreads();

        // gate math + state update (64 threads: 2 hidden units x 32 batch)
        if (tid < 64) {
            int w  = tid >> 5;
            int bb = tid & 31;
            float gi = gates_s[0 + w][bb];
            float gg = gates_s[2 + w][bb];
            float gf = gates_s[4 + w][bb];
            float go = gates_s[6 + w][bb];
            float cc = sigf(gf + 1.f) * cst[w][bb] + sigf(gi) * tanhf(gg);
            cst[w][bb] = cc;
            float hh = sigf(go) * tanhf(cc);
            g_h[(t + 1) & 1][bb * H_ + c2 + w] = hh;
        }
        __syncthreads();

        // publish: release-arrive on global counter
        if (tid == 0) {
            asm volatile("red.release.gpu.add.u32 [%0], 1;" :: "l"(&g_ctr) : "memory");
        }
    }
}

// ---------------- kernel 3: out = (h @ Wfc + bfc) @ Wout + bout ----------------
__global__ void __launch_bounds__(256) k_fc(const float* __restrict__ Wfc,
                                            const float* __restrict__ bfc,
                                            const float* __restrict__ Wout,
                                            const float* __restrict__ bout,
                                            float* __restrict__ out) {
    __shared__ float tmp[H_];
    int b = blockIdx.x;
    int j = threadIdx.x;
    const float* h = &g_h[0][b * H_];   // final h lives in buffer (4095+1)&1 = 0
    float s = bfc[j];
    #pragma unroll 8
    for (int k = 0; k < H_; k++) s += h[k] * Wfc[(size_t)k * H_ + j];
    tmp[j] = s;
    __syncthreads();
    if (j < HOR_) {
        float o = bout[j];
        #pragma unroll 8
        for (int k = 0; k < H_; k++) o += tmp[k] * Wout[(size_t)k * HOR_ + j];
        out[b * HOR_ + j] = o;
    }
}

// ---------------- launch ----------------
extern "C" void kernel_launch(void* const* d_in, const int* in_sizes, int n_in,
                              void* d_out, int out_size) {
    const float* x      = (const float*)d_in[0];
    const float* W_lstm = (const float*)d_in[1];
    const float* b_lstm = (const float*)d_in[2];
    const float* W_fc   = (const float*)d_in[3];
    const float* b_fc   = (const float*)d_in[4];
    const float* W_out  = (const float*)d_in[5];
    const float* b_out  = (const float*)d_in[6];
    float* out = (float*)d_out;

    k_init<<<1, 256>>>();
    k_xgemm<<<dim3(T_, 16), 256>>>(x, W_lstm, b_lstm);
    k_rnn<<<GCTA, 256>>>(W_lstm);
    k_fc<<<B_, 256>>>(W_fc, b_fc, W_out, b_out, out);
}

// round 3
// speedup vs baseline: 1.2559x; 1.2559x over previous
#include <cuda_runtime.h>
#include <cstdint>

#define B_    32
#define T_    4096
#define D_    256
#define H_    256
#define G4_   1024
#define HOR_  24

typedef unsigned long long ull;

// ---------------- device scratch (static; no runtime allocation) ----------------
__device__ __align__(16) float g_XG[(size_t)T_ * G4_ * B_];   // [t][n][b] fp32, 512 MB
__device__ __align__(16) float g_h[B_ * H_];                  // final hidden state [b][j]

// ---------------- helpers ----------------
__device__ __forceinline__ ull pack2(float x, float y) {
    ull r;
    asm("mov.b64 %0, {%1, %2};" : "=l"(r) : "f"(x), "f"(y));
    return r;
}
__device__ __forceinline__ void unpack2(ull v, float& x, float& y) {
    asm("mov.b64 {%0, %1}, %2;" : "=f"(x), "=f"(y) : "l"(v));
}
__device__ __forceinline__ ull fma2(ull a, ull w, ull x) {
    asm("fma.rn.f32x2 %0, %1, %2, %0;" : "+l"(a) : "l"(w), "l"(x));
    return a;
}
__device__ __forceinline__ float sigf(float x) { return 1.f / (1.f + __expf(-x)); }
__device__ __forceinline__ unsigned smem_u32(const void* p) {
    return (unsigned)__cvta_generic_to_shared(p);
}

// ---------------- kernel 1: XG[t][n][b] = sum_k x[b][t][k]*W[k][n] + b_lstm[n] ----------------
// grid (T_, 16), 256 threads. Each CTA: one t, 64 n-columns.
__global__ void __launch_bounds__(256) k_xgemm(const float* __restrict__ x,
                                               const float* __restrict__ W,
                                               const float* __restrict__ bl) {
    __shared__ __align__(16) float xs[256][32];   // [k][b]
    __shared__ __align__(16) float ws[32][64];    // [kk][nn]
    int t  = blockIdx.x;
    int n0 = blockIdx.y * 64;
    int tid = threadIdx.x;
    int b  = tid & 31;
    int ng = tid >> 5;   // 0..7, 8 n-values per thread

    // load x_t [32 rows of 256] transposed into xs[k][b]
    {
        int br = tid >> 3;           // row 0..31
        int kq = (tid & 7) * 32;     // k offset
        const float4* src = (const float4*)(x + ((size_t)br * T_ + t) * D_ + kq);
        #pragma unroll
        for (int q = 0; q < 8; q++) {
            float4 v = src[q];
            int k = kq + q * 4;
            xs[k][br] = v.x; xs[k + 1][br] = v.y; xs[k + 2][br] = v.z; xs[k + 3][br] = v.w;
        }
    }

    ull acc[4];
    #pragma unroll
    for (int p = 0; p < 4; p++) acc[p] = 0ull;

    for (int kc = 0; kc < 8; kc++) {
        __syncthreads();
        for (int i = tid; i < 2048; i += 256) {
            int kk = i >> 6, nn = i & 63;
            ws[kk][nn] = W[(size_t)(kc * 32 + kk) * G4_ + n0 + nn];
        }
        __syncthreads();
        #pragma unroll
        for (int kk = 0; kk < 32; kk++) {
            float xv = xs[kc * 32 + kk][b];
            ull xx = pack2(xv, xv);
            const ull* wp = (const ull*)&ws[kk][ng * 8];
            acc[0] = fma2(acc[0], wp[0], xx);
            acc[1] = fma2(acc[1], wp[1], xx);
            acc[2] = fma2(acc[2], wp[2], xx);
            acc[3] = fma2(acc[3], wp[3], xx);
        }
    }

    size_t base = (size_t)t * (G4_ * B_) + (size_t)(n0 + ng * 8) * B_ + b;
    #pragma unroll
    for (int p = 0; p < 4; p++) {
        float ax, ay;
        unpack2(acc[p], ax, ay);
        int n = n0 + ng * 8 + 2 * p;
        g_XG[base + (size_t)(2 * p) * B_]     = ax + bl[n];
        g_XG[base + (size_t)(2 * p + 1) * B_] = ay + bl[n + 1];
    }
}

// ---------------- kernel 2: clustered LSTM recurrence ----------------
// 16 clusters x 8 CTAs. Cluster g owns batch pair {2g, 2g+1}.
// CTA rank r owns hidden slice j in [32r, 32r+32) -> 4 gates x 32 j = 128 gate rows.
// Thread (w = tid>>5, l = tid&31): K-chunk [32w, 32w+32), hidden j = 32r + l.
// First 16 K of the chunk: register-stationary weights; last 16 K: streamed from SMEM.
struct RnnSmem {
    ull   Wst[8][8][4][32];    // [kh][pair][gate][l] streamed weight half, 64 KB
    float red[8][4][2][32];    // [kh][gate][b][l] partials, 8 KB
    float hs[2][2][H_];        // [parity][b][j] hidden state, 4 KB
    ull   xg_s[4][32];         // [gate][l] packed XG pair (b0,b1), 1 KB
    float gs[4][2][32];        // [gate][b][l] gate sums, 1 KB
};

__global__ void __launch_bounds__(256, 1) __cluster_dims__(8, 1, 1)
k_rnn(const float* __restrict__ W) {
    extern __shared__ __align__(16) unsigned char smem_raw[];
    RnnSmem* S = (RnnSmem*)smem_raw;

    const int tid = threadIdx.x;
    const int w   = tid >> 5;        // 0..7 K-chunk
    const int l   = tid & 31;        // 0..31 hidden-lane
    const int r   = blockIdx.x & 7;  // cluster rank
    const int g   = blockIdx.x >> 3; // cluster id -> batch pair {2g, 2g+1}
    const int kbase = w * 32;

    // gate-row indices for this thread's hidden unit
    int nq[4];
    #pragma unroll
    for (int q = 0; q < 4; q++) nq[q] = q * 256 + r * 32 + l;

    // stationary weights: regs (K sub [kbase, kbase+16)) + SMEM stream (K sub [kbase+16, kbase+32))
    ull wreg[32];
    #pragma unroll
    for (int q = 0; q < 4; q++) {
        #pragma unroll
        for (int p = 0; p < 8; p++) {
            int k = kbase + 2 * p;
            wreg[q * 8 + p] = pack2(W[(size_t)(D_ + k) * G4_ + nq[q]],
                                    W[(size_t)(D_ + k + 1) * G4_ + nq[q]]);
            int ks = kbase + 16 + 2 * p;
            S->Wst[w][p][q][l] = pack2(W[(size_t)(D_ + ks) * G4_ + nq[q]],
                                       W[(size_t)(D_ + ks + 1) * G4_ + nq[q]]);
        }
    }
    // zero only parity-0 h (parity-1 gets remote-stored before first read)
    for (int i = tid; i < 2 * H_; i += 256) ((float*)S->hs[0])[i] = 0.f;
    float c_state = 0.f;   // cell state, valid for tid < 64
    __syncthreads();

    // XG prefetch mapping for tid < 128: gate q = tid>>5, lane l
    const float* pf = g_XG + (size_t)(((tid >> 5) & 3) * 256 + r * 32 + l) * B_ + 2 * g;

    for (int t = 0; t < T_; ++t) {
        // prefetch this step's XG pair (b0,b1) early; DRAM latency hidden under GEMV
        ull xv = 0;
        if (tid < 128) xv = *(const ull*)(pf + (size_t)t * (G4_ * B_));

        const int par = t & 1;
        const ull* hp0 = (const ull*)&S->hs[par][0][kbase];
        const ull* hp1 = (const ull*)&S->hs[par][1][kbase];

        ull acc[8];
        #pragma unroll
        for (int i = 0; i < 8; i++) acc[i] = 0ull;

        // register-weight half
        #pragma unroll
        for (int p = 0; p < 8; p++) {
            ull h0 = hp0[p];
            ull h1 = hp1[p];
            #pragma unroll
            for (int q = 0; q < 4; q++) {
                acc[2 * q]     = fma2(acc[2 * q],     wreg[q * 8 + p], h0);
                acc[2 * q + 1] = fma2(acc[2 * q + 1], wreg[q * 8 + p], h1);
            }
        }
        // streamed-weight half
        #pragma unroll
        for (int p = 0; p < 8; p++) {
            ull h0 = hp0[8 + p];
            ull h1 = hp1[8 + p];
            #pragma unroll
            for (int q = 0; q < 4; q++) {
                ull wv = S->Wst[w][p][q][l];
                acc[2 * q]     = fma2(acc[2 * q],     wv, h0);
                acc[2 * q + 1] = fma2(acc[2 * q + 1], wv, h1);
            }
        }

        // write K-chunk partials
        #pragma unroll
        for (int q = 0; q < 4; q++) {
            float a0, a1;
            unpack2(acc[2 * q], a0, a1);
            S->red[w][q][0][l] = a0 + a1;
            unpack2(acc[2 * q + 1], a0, a1);
            S->red[w][q][1][l] = a0 + a1;
        }
        if (tid < 128) S->xg_s[(tid >> 5) & 3][l] = xv;
        __syncthreads();

        // phase 2: reduce over 8 K-chunks; thread -> (gate, b, l)
        {
            int q2 = tid >> 6;
            int b2 = (tid >> 5) & 1;
            float s = 0.f;
            #pragma unroll
            for (int kh = 0; kh < 8; kh++) s += S->red[kh][q2][b2][l];
            float x0, x1;
            unpack2(S->xg_s[q2][l], x0, x1);
            S->gs[q2][b2][l] = s + (b2 ? x1 : x0);
        }
        __syncthreads();

        // phase 3: activations + state update + DSMEM broadcast (64 threads: b x l)
        if (tid < 64) {
            int b3 = tid >> 5;
            float gi = S->gs[0][b3][l];
            float gG = S->gs[1][b3][l];
            float gf = S->gs[2][b3][l];
            float go = S->gs[3][b3][l];
            c_state = sigf(gf + 1.f) * c_state + sigf(gi) * tanhf(gG);
            float h = sigf(go) * tanhf(c_state);

            unsigned hbits = __float_as_uint(h);
            unsigned laddr = smem_u32(&S->hs[(t + 1) & 1][b3][r * 32 + l]);
            #pragma unroll
            for (int dst = 0; dst < 8; dst++) {
                unsigned raddr;
                asm volatile("mapa.shared::cluster.u32 %0, %1, %2;"
                             : "=r"(raddr) : "r"(laddr), "r"(dst));
                asm volatile("st.shared::cluster.u32 [%0], %1;"
                             :: "r"(raddr), "r"(hbits) : "memory");
            }
            if (t == T_ - 1) g_h[(2 * g + b3) * H_ + r * 32 + l] = h;
        }

        // cluster barrier: release orders the DSMEM stores; acquire makes them visible
        asm volatile("barrier.cluster.arrive.aligned;" ::: "memory");
        asm volatile("barrier.cluster.wait.aligned;"   ::: "memory");
    }
}

// ---------------- kernel 3: out = (h @ Wfc + bfc) @ Wout + bout ----------------
__global__ void __launch_bounds__(256) k_fc(const float* __restrict__ Wfc,
                                            const float* __restrict__ bfc,
                                            const float* __restrict__ Wout,
                                            const float* __restrict__ bout,
                                            float* __restrict__ out) {
    __shared__ float tmp[H_];
    int b = blockIdx.x;
    int j = threadIdx.x;
    const float* h = &g_h[b * H_];
    float s = bfc[j];
    #pragma unroll 8
    for (int k = 0; k < H_; k++) s += h[k] * Wfc[(size_t)k * H_ + j];
    tmp[j] = s;
    __syncthreads();
    if (j < HOR_) {
        float o = bout[j];
        #pragma unroll 8
        for (int k = 0; k < H_; k++) o += tmp[k] * Wout[(size_t)k * HOR_ + j];
        out[b * HOR_ + j] = o;
    }
}

// ---------------- launch ----------------
extern "C" void kernel_launch(void* const* d_in, const int* in_sizes, int n_in,
                              void* d_out, int out_size) {
    const float* x      = (const float*)d_in[0];
    const float* W_lstm = (const float*)d_in[1];
    const float* b_lstm = (const float*)d_in[2];
    const float* W_fc   = (const float*)d_in[3];
    const float* b_fc   = (const float*)d_in[4];
    const float* W_out  = (const float*)d_in[5];
    const float* b_out  = (const float*)d_in[6];
    float* out = (float*)d_out;

    cudaFuncSetAttribute(k_rnn, cudaFuncAttributeMaxDynamicSharedMemorySize,
                         (int)sizeof(RnnSmem));

    k_xgemm<<<dim3(T_, 16), 256>>>(x, W_lstm, b_lstm);
    k_rnn<<<128, 256, sizeof(RnnSmem)>>>(W_lstm);
    k_fc<<<B_, 256>>>(W_fc, b_fc, W_out, b_out, out);
}

// round 4
// speedup vs baseline: 2.0226x; 1.6105x over previous
#include <cuda_runtime.h>
#include <cstdint>

#define B_    32
#define T_    4096
#define D_    256
#define H_    256
#define G4_   1024
#define HOR_  24

typedef unsigned long long ull;

// ---------------- device scratch (static; no runtime allocation) ----------------
__device__ __align__(16) float g_XG[(size_t)B_ * T_ * G4_];   // [b][t][n] fp32, 512 MB
__device__ __align__(16) float g_h[B_ * H_];                  // final hidden state [b][j]

// ---------------- helpers ----------------
__device__ __forceinline__ ull pack2(float x, float y) {
    ull r;
    asm("mov.b64 %0, {%1, %2};" : "=l"(r) : "f"(x), "f"(y));
    return r;
}
__device__ __forceinline__ void unpack2(ull v, float& x, float& y) {
    asm("mov.b64 {%0, %1}, %2;" : "=f"(x), "=f"(y) : "l"(v));
}
__device__ __forceinline__ ull fma2(ull a, ull w, ull x) {
    asm("fma.rn.f32x2 %0, %1, %2, %0;" : "+l"(a) : "l"(w), "l"(x));
    return a;
}
__device__ __forceinline__ float ex2f(float x) {
    float y; asm("ex2.approx.f32 %0, %1;" : "=f"(y) : "f"(x)); return y;
}
__device__ __forceinline__ float rcpf(float x) {
    float y; asm("rcp.approx.f32 %0, %1;" : "=f"(y) : "f"(x)); return y;
}
// sigmoid/tanh via MUFU only (EX2 + RCP), ~1e-6 rel err
__device__ __forceinline__ float sigf(float x) {
    return rcpf(1.f + ex2f(-1.4426950408889634f * x));
}
__device__ __forceinline__ float tanh_f(float x) {
    return fmaf(2.f, rcpf(1.f + ex2f(-2.8853900817779268f * x)), -1.f);
}
__device__ __forceinline__ unsigned smem_u32(const void* p) {
    return (unsigned)__cvta_generic_to_shared(p);
}

// ---------------- kernel 1: XG[b][t][n] = sum_k x[b][t][k]*W[k][n] + b_lstm[n] ----------------
// grid (T_, 16), 256 threads. Each CTA: one t, 64 n-columns, all 32 b.
__global__ void __launch_bounds__(256) k_xgemm(const float* __restrict__ x,
                                               const float* __restrict__ W,
                                               const float* __restrict__ bl) {
    __shared__ __align__(16) float xs[256][32];   // [k][b]
    __shared__ __align__(16) float ws[32][64];    // [kk][nn]
    int t  = blockIdx.x;
    int n0 = blockIdx.y * 64;
    int tid = threadIdx.x;
    int b  = tid & 31;
    int ng = tid >> 5;   // 0..7, 8 n-values per thread

    // load x_t [32 rows of 256] transposed into xs[k][b]
    {
        int br = tid >> 3;           // batch row 0..31
        int kq = (tid & 7) * 32;     // k offset
        const float4* src = (const float4*)(x + ((size_t)br * T_ + t) * D_ + kq);
        #pragma unroll
        for (int q = 0; q < 8; q++) {
            float4 v = src[q];
            int k = kq + q * 4;
            xs[k][br] = v.x; xs[k + 1][br] = v.y; xs[k + 2][br] = v.z; xs[k + 3][br] = v.w;
        }
    }

    ull acc[4];
    #pragma unroll
    for (int p = 0; p < 4; p++) acc[p] = 0ull;

    for (int kc = 0; kc < 8; kc++) {
        __syncthreads();
        for (int i = tid; i < 2048; i += 256) {
            int kk = i >> 6, nn = i & 63;
            ws[kk][nn] = W[(size_t)(kc * 32 + kk) * G4_ + n0 + nn];
        }
        __syncthreads();
        #pragma unroll
        for (int kk = 0; kk < 32; kk++) {
            float xv = xs[kc * 32 + kk][b];
            ull xx = pack2(xv, xv);
            const ull* wp = (const ull*)&ws[kk][ng * 8];
            acc[0] = fma2(acc[0], wp[0], xx);
            acc[1] = fma2(acc[1], wp[1], xx);
            acc[2] = fma2(acc[2], wp[2], xx);
            acc[3] = fma2(acc[3], wp[3], xx);
        }
    }

    // write 8 consecutive n for this (b, t)
    int n = n0 + ng * 8;
    float o[8];
    #pragma unroll
    for (int p = 0; p < 4; p++) {
        unpack2(acc[p], o[2 * p], o[2 * p + 1]);
        o[2 * p]     += bl[n + 2 * p];
        o[2 * p + 1] += bl[n + 2 * p + 1];
    }
    float* dst = g_XG + ((size_t)b * T_ + t) * G4_ + n;
    *(float4*)(dst)     = make_float4(o[0], o[1], o[2], o[3]);
    *(float4*)(dst + 4) = make_float4(o[4], o[5], o[6], o[7]);
}

// ---------------- kernel 2: clustered LSTM recurrence ----------------
// 32 clusters x 8 CTAs, 2 CTAs per SM (occupancy 2 hides barrier/epilogue latency).
// Cluster g owns batch element b=g. CTA rank r owns hidden slice j in [32r, 32r+32).
// Thread (w = tid>>5, l = tid&31): K-chunk [32w, 32w+32), hidden j = 32r + l, 4 gates.
// Weight pairs 0..9 of each gate register-stationary; pairs 10..15 streamed from SMEM.
struct RnnSmem {
    ull   Wst[8][6][4][32];    // [w][p][q][l] streamed weight pairs, 48 KB
    float red[8][4][32];       // [w][q][l] K-chunk partials, 4 KB
    float hs[2][H_];           // [parity][j] hidden state, 2 KB
    float xg_s[4][32];         // [q][l] staged XG, 0.5 KB
};

__global__ void __launch_bounds__(256, 2) __cluster_dims__(8, 1, 1)
k_rnn(const float* __restrict__ W) {
    extern __shared__ __align__(16) unsigned char smem_raw[];
    RnnSmem* S = (RnnSmem*)smem_raw;

    const int tid = threadIdx.x;
    const int w   = tid >> 5;        // 0..7 K-chunk
    const int l   = tid & 31;        // 0..31 hidden lane
    const int r   = blockIdx.x & 7;  // cluster rank
    const int g   = blockIdx.x >> 3; // cluster id == batch element
    const int kbase = w * 32;
    const int j   = r * 32 + l;

    // stationary weights: 40 reg pairs + 24 smem pairs per thread
    ull wreg[40];
    #pragma unroll
    for (int q = 0; q < 4; q++) {
        int n = q * 256 + j;
        #pragma unroll
        for (int p = 0; p < 10; p++) {
            int k = kbase + 2 * p;
            wreg[q * 10 + p] = pack2(W[(size_t)(D_ + k) * G4_ + n],
                                     W[(size_t)(D_ + k + 1) * G4_ + n]);
        }
        #pragma unroll
        for (int p = 0; p < 6; p++) {
            int k = kbase + 20 + 2 * p;
            S->Wst[w][p][q][l] = pack2(W[(size_t)(D_ + k) * G4_ + n],
                                       W[(size_t)(D_ + k + 1) * G4_ + n]);
        }
    }
    for (int i = tid; i < H_; i += 256) S->hs[0][i] = 0.f;
    float c_state = 0.f;   // valid in warp 0
    __syncthreads();

    // XG stream for warps 0..3: XG[g][t][w*256 + r*32 + l], one 128B line per warp per step
    const float* xgp = g_XG + ((size_t)g * T_) * G4_ + w * 256 + r * 32 + l;
    float xv = (tid < 128) ? __ldcs(xgp) : 0.f;

    #pragma unroll 1
    for (int t = 0; t < T_; ++t) {
        // stage current XG; prefetch next step's (latency hidden under GEMV)
        if (tid < 128) {
            S->xg_s[w][l] = xv;
            if (t + 1 < T_) xv = __ldcs(xgp + (size_t)(t + 1) * G4_);
        }

        const ull* hp = (const ull*)&S->hs[t & 1][kbase];
        ull acc0 = 0, acc1 = 0, acc2 = 0, acc3 = 0;

        #pragma unroll
        for (int p = 0; p < 10; p++) {
            ull h = hp[p];
            acc0 = fma2(acc0, wreg[p],      h);
            acc1 = fma2(acc1, wreg[10 + p], h);
            acc2 = fma2(acc2, wreg[20 + p], h);
            acc3 = fma2(acc3, wreg[30 + p], h);
        }
        const ull* wst = &S->Wst[w][0][0][l];
        #pragma unroll
        for (int p = 0; p < 6; p++) {
            ull h = hp[10 + p];
            acc0 = fma2(acc0, wst[p * 128 + 0],  h);
            acc1 = fma2(acc1, wst[p * 128 + 32], h);
            acc2 = fma2(acc2, wst[p * 128 + 64], h);
            acc3 = fma2(acc3, wst[p * 128 + 96], h);
        }

        float a0x, a0y, a1x, a1y, a2x, a2y, a3x, a3y;
        unpack2(acc0, a0x, a0y);
        unpack2(acc1, a1x, a1y);
        unpack2(acc2, a2x, a2y);
        unpack2(acc3, a3x, a3y);
        S->red[w][0][l] = a0x + a0y;
        S->red[w][1][l] = a1x + a1y;
        S->red[w][2][l] = a2x + a2y;
        S->red[w][3][l] = a3x + a3y;
        __syncthreads();

        // warp 0: reduce over 8 K-chunks, activations, broadcast h
        if (w == 0) {
            float gsum[4];
            #pragma unroll
            for (int q = 0; q < 4; q++) {
                float s = S->xg_s[q][l];
                #pragma unroll
                for (int kh = 0; kh < 8; kh++) s += S->red[kh][q][l];
                gsum[q] = s;
            }
            c_state = sigf(gsum[2] + 1.f) * c_state + sigf(gsum[0]) * tanh_f(gsum[1]);
            float h = sigf(gsum[3]) * tanh_f(c_state);

            unsigned hbits = __float_as_uint(h);
            unsigned laddr = smem_u32(&S->hs[(t + 1) & 1][j]);
            #pragma unroll
            for (int dst = 0; dst < 8; dst++) {
                unsigned raddr;
                asm volatile("mapa.shared::cluster.u32 %0, %1, %2;"
                             : "=r"(raddr) : "r"(laddr), "r"(dst));
                asm volatile("st.shared::cluster.u32 [%0], %1;"
                             :: "r"(raddr), "r"(hbits) : "memory");
            }
            if (t == T_ - 1) g_h[g * H_ + j] = h;
        }

        // cluster barrier: release orders warp 0's DSMEM stores; wait makes them visible
        asm volatile("barrier.cluster.arrive.aligned;" ::: "memory");
        asm volatile("barrier.cluster.wait.aligned;"   ::: "memory");
    }
}

// ---------------- kernel 3: out = (h @ Wfc + bfc) @ Wout + bout ----------------
__global__ void __launch_bounds__(256) k_fc(const float* __restrict__ Wfc,
                                            const float* __restrict__ bfc,
                                            const float* __restrict__ Wout,
                                            const float* __restrict__ bout,
                                            float* __restrict__ out) {
    __shared__ float tmp[H_];
    int b = blockIdx.x;
    int jj = threadIdx.x;
    const float* h = &g_h[b * H_];
    float s = bfc[jj];
    #pragma unroll 8
    for (int k = 0; k < H_; k++) s += h[k] * Wfc[(size_t)k * H_ + jj];
    tmp[jj] = s;
    __syncthreads();
    if (jj < HOR_) {
        float o = bout[jj];
        #pragma unroll 8
        for (int k = 0; k < H_; k++) o += tmp[k] * Wout[(size_t)k * HOR_ + jj];
        out[b * HOR_ + jj] = o;
    }
}

// ---------------- launch ----------------
extern "C" void kernel_launch(void* const* d_in, const int* in_sizes, int n_in,
                              void* d_out, int out_size) {
    const float* x      = (const float*)d_in[0];
    const float* W_lstm = (const float*)d_in[1];
    const float* b_lstm = (const float*)d_in[2];
    const float* W_fc   = (const float*)d_in[3];
    const float* b_fc   = (const float*)d_in[4];
    const float* W_out  = (const float*)d_in[5];
    const float* b_out  = (const float*)d_in[6];
    float* out = (float*)d_out;

    cudaFuncSetAttribute(k_rnn, cudaFuncAttributeMaxDynamicSharedMemorySize,
                         (int)sizeof(RnnSmem));

    k_xgemm<<<dim3(T_, 16), 256>>>(x, W_lstm, b_lstm);
    k_rnn<<<256, 256, sizeof(RnnSmem)>>>(W_lstm);
    k_fc<<<B_, 256>>>(W_fc, b_fc, W_out, b_out, out);
}

// round 5
// speedup vs baseline: 3.1360x; 1.5505x over previous
#include <cuda_runtime.h>
#include <cstdint>

#define B_    32
#define T_    4096
#define D_    256
#define H_    256
#define G4_   1024
#define HOR_  24

typedef unsigned long long ull;

// ---------------- device scratch (static; no runtime allocation) ----------------
__device__ __align__(16) float g_XG[(size_t)B_ * T_ * G4_];   // [m=b*T+t][n] fp32, 512 MB
__device__ __align__(16) float g_h[B_ * H_];                  // final hidden state [b][j]

// ---------------- helpers ----------------
__device__ __forceinline__ ull pack2(float x, float y) {
    ull r;
    asm("mov.b64 %0, {%1, %2};" : "=l"(r) : "f"(x), "f"(y));
    return r;
}
__device__ __forceinline__ void unpack2(ull v, float& x, float& y) {
    asm("mov.b64 {%0, %1}, %2;" : "=f"(x), "=f"(y) : "l"(v));
}
__device__ __forceinline__ ull fma2(ull a, ull w, ull x) {
    asm("fma.rn.f32x2 %0, %1, %2, %0;" : "+l"(a) : "l"(w), "l"(x));
    return a;
}
__device__ __forceinline__ float ex2f(float x) {
    float y; asm("ex2.approx.f32 %0, %1;" : "=f"(y) : "f"(x)); return y;
}
__device__ __forceinline__ float rcpf(float x) {
    float y; asm("rcp.approx.f32 %0, %1;" : "=f"(y) : "f"(x)); return y;
}
__device__ __forceinline__ float sigf(float x) {
    return rcpf(1.f + ex2f(-1.4426950408889634f * x));
}
__device__ __forceinline__ float tanh_f(float x) {
    return fmaf(2.f, rcpf(1.f + ex2f(-2.8853900817779268f * x)), -1.f);
}
__device__ __forceinline__ unsigned smem_u32(const void* p) {
    return (unsigned)__cvta_generic_to_shared(p);
}
__device__ __forceinline__ void mbar_wait_cluster(unsigned mb, unsigned par) {
    asm volatile(
        "{\n\t"
        ".reg .pred P;\n\t"
        "WL_%=:\n\t"
        "mbarrier.try_wait.parity.acquire.cluster.shared::cta.b64 P, [%0], %1, 0x989680;\n\t"
        "@!P bra WL_%=;\n\t"
        "}"
        :: "r"(mb), "r"(par) : "memory");
}

// ---------------- kernel 1: SGEMM  XG[m][n] = A[m][k] @ W[k][n] + bl[n] ----------------
// M=131072, N=1024, K=256. Tile 128M x 64N, K-tile 16, double-buffered.
// 256 threads; each thread 8M x 4N with M-pairs packed in f32x2.
#define MT 128
#define NT 64
#define KT 16

__global__ void __launch_bounds__(256) k_xgemm(const float* __restrict__ A,
                                               const float* __restrict__ W,
                                               const float* __restrict__ bl) {
    __shared__ __align__(16) float As[2][KT][MT];   // 16 KB
    __shared__ __align__(16) float Bs[2][KT][NT];   // 8 KB
    const int tid = threadIdx.x;
    const int m0 = blockIdx.x * MT;
    const int n0 = blockIdx.y * NT;

    // A loader: thread covers rows {tid>>2, 64+(tid>>2)}, k-sub (tid&3)*4
    const int ar0 = tid >> 2;
    const int akc = (tid & 3) * 4;
    // B loader: one float4
    const int bk = tid >> 4;
    const int bn = (tid & 15) * 4;
    // compute mapping
    const int mt = tid >> 4;   // rows mt*8 .. +8
    const int nt = tid & 15;   // cols nt*4 .. +4

    const float* Ar0 = A + (size_t)(m0 + ar0) * D_ + akc;
    const float* Ar1 = A + (size_t)(m0 + 64 + ar0) * D_ + akc;
    const float* Wp  = W + (size_t)bk * G4_ + n0 + bn;

    float4 a0 = *(const float4*)(Ar0);
    float4 a1 = *(const float4*)(Ar1);
    float4 b0 = *(const float4*)(Wp);
    #pragma unroll
    for (int i = 0; i < 4; i++) {
        As[0][akc + i][ar0]      = ((const float*)&a0)[i];
        As[0][akc + i][64 + ar0] = ((const float*)&a1)[i];
    }
    *(float4*)&Bs[0][bk][bn] = b0;
    __syncthreads();

    ull acc[4][4];
    #pragma unroll
    for (int p = 0; p < 4; p++)
        #pragma unroll
        for (int n = 0; n < 4; n++) acc[p][n] = 0ull;

    #pragma unroll 1
    for (int kt = 0; kt < D_ / KT; kt++) {
        const int cur = kt & 1, nxt = cur ^ 1;
        if (kt + 1 < D_ / KT) {
            a0 = *(const float4*)(Ar0 + (kt + 1) * KT);
            a1 = *(const float4*)(Ar1 + (kt + 1) * KT);
            b0 = *(const float4*)(Wp + (size_t)(kt + 1) * KT * G4_);
        }
        #pragma unroll
        for (int k = 0; k < KT; k++) {
            const ull* ap = (const ull*)&As[cur][k][mt * 8];
            const float* bp = &Bs[cur][k][nt * 4];
            ull am0 = ap[0], am1 = ap[1], am2 = ap[2], am3 = ap[3];
            #pragma unroll
            for (int n = 0; n < 4; n++) {
                ull bb = pack2(bp[n], bp[n]);
                acc[0][n] = fma2(acc[0][n], am0, bb);
                acc[1][n] = fma2(acc[1][n], am1, bb);
                acc[2][n] = fma2(acc[2][n], am2, bb);
                acc[3][n] = fma2(acc[3][n], am3, bb);
            }
        }
        if (kt + 1 < D_ / KT) {
            #pragma unroll
            for (int i = 0; i < 4; i++) {
                As[nxt][akc + i][ar0]      = ((const float*)&a0)[i];
                As[nxt][akc + i][64 + ar0] = ((const float*)&a1)[i];
            }
            *(float4*)&Bs[nxt][bk][bn] = b0;
            __syncthreads();
        }
    }

    float bias[4];
    #pragma unroll
    for (int n = 0; n < 4; n++) bias[n] = bl[n0 + nt * 4 + n];
    float* Cr = g_XG + (size_t)(m0 + mt * 8) * G4_ + n0 + nt * 4;
    #pragma unroll
    for (int p = 0; p < 4; p++) {
        float e[4], o[4];
        #pragma unroll
        for (int n = 0; n < 4; n++) {
            unpack2(acc[p][n], e[n], o[n]);
            e[n] += bias[n]; o[n] += bias[n];
        }
        *(float4*)(Cr + (size_t)(2 * p) * G4_)     = make_float4(e[0], e[1], e[2], e[3]);
        *(float4*)(Cr + (size_t)(2 * p + 1) * G4_) = make_float4(o[0], o[1], o[2], o[3]);
    }
}

// ---------------- kernel 2: clustered LSTM recurrence (mbarrier sync) ----------------
// 32 clusters x 8 CTAs, 2 CTAs/SM. Cluster g owns batch b=g. CTA rank r owns j in [32r,32r+32).
// Sync per step: warp0 lanes st.async h to all 8 ranks with mbarrier tx completion
// (expect 8*32*4 = 1024 B + 1 self arrive). Two mbars alternate by step parity.
struct RnnSmem {
    ull   Wst[8][6][4][32];    // [w][p][q][l] streamed weight pairs, 48 KB
    float red[8][4][32];       // [w][q][l] K-chunk partials, 4 KB
    float hs[2][H_];           // [parity][j] hidden state, 2 KB
    float xg_s[4][32];         // [q][l] staged XG, 0.5 KB
    ull   mbar[2];
};

__global__ void __launch_bounds__(256, 2) __cluster_dims__(8, 1, 1)
k_rnn(const float* __restrict__ W) {
    extern __shared__ __align__(16) unsigned char smem_raw[];
    RnnSmem* S = (RnnSmem*)smem_raw;

    const int tid = threadIdx.x;
    const int w   = tid >> 5;
    const int l   = tid & 31;
    const int r   = blockIdx.x & 7;
    const int g   = blockIdx.x >> 3;
    const int kbase = w * 32;
    const int j   = r * 32 + l;

    // stationary weights: 40 reg pairs + 24 smem pairs per thread
    ull wreg[40];
    #pragma unroll
    for (int q = 0; q < 4; q++) {
        int n = q * 256 + j;
        #pragma unroll
        for (int p = 0; p < 10; p++) {
            int k = kbase + 2 * p;
            wreg[q * 10 + p] = pack2(W[(size_t)(D_ + k) * G4_ + n],
                                     W[(size_t)(D_ + k + 1) * G4_ + n]);
        }
        #pragma unroll
        for (int p = 0; p < 6; p++) {
            int k = kbase + 20 + 2 * p;
            S->Wst[w][p][q][l] = pack2(W[(size_t)(D_ + k) * G4_ + n],
                                       W[(size_t)(D_ + k + 1) * G4_ + n]);
        }
    }
    for (int i = tid; i < H_; i += 256) S->hs[0][i] = 0.f;
    float c_state = 0.f;

    const unsigned sbase  = smem_u32(S);
    const unsigned hs_off = (unsigned)((char*)&S->hs[0][0] - (char*)S);
    const unsigned mb_off = (unsigned)((char*)&S->mbar[0] - (char*)S);

    if (tid == 0) {
        asm volatile("mbarrier.init.shared.b64 [%0], 1;" :: "r"(sbase + mb_off)     : "memory");
        asm volatile("mbarrier.init.shared.b64 [%0], 1;" :: "r"(sbase + mb_off + 8) : "memory");
    }
    __syncthreads();
    // all mbarriers across the cluster must be live before any st.async targets them
    asm volatile("barrier.cluster.arrive.aligned;" ::: "memory");
    asm volatile("barrier.cluster.wait.aligned;"   ::: "memory");

    // remote smem base for each rank (offset arithmetic valid within mapped window)
    unsigned rbase[8];
    #pragma unroll
    for (int d = 0; d < 8; d++)
        asm("mapa.shared::cluster.u32 %0, %1, %2;" : "=r"(rbase[d]) : "r"(sbase), "r"(d));

    // XG stream for warps 0..3: one 128B line per warp per step
    const float* xgp = g_XG + (size_t)g * T_ * G4_ + w * 256 + j;
    float xv = (tid < 128) ? __ldcs(xgp) : 0.f;

    #pragma unroll 1
    for (int t = 0; t < T_; ++t) {
        if (t > 0)
            mbar_wait_cluster(sbase + mb_off + ((t - 1) & 1) * 8, ((t - 1) >> 1) & 1);

        if (tid < 128) {
            S->xg_s[w][l] = xv;
            if (t + 1 < T_) xv = __ldcs(xgp + (size_t)(t + 1) * G4_);
        }

        const ull* hp = (const ull*)&S->hs[t & 1][kbase];
        ull acc0 = 0, acc1 = 0, acc2 = 0, acc3 = 0;

        #pragma unroll
        for (int p = 0; p < 10; p++) {
            ull h = hp[p];
            acc0 = fma2(acc0, wreg[p],      h);
            acc1 = fma2(acc1, wreg[10 + p], h);
            acc2 = fma2(acc2, wreg[20 + p], h);
            acc3 = fma2(acc3, wreg[30 + p], h);
        }
        const ull* wst = &S->Wst[w][0][0][l];
        #pragma unroll
        for (int p = 0; p < 6; p++) {
            ull h = hp[10 + p];
            acc0 = fma2(acc0, wst[p * 128 + 0],  h);
            acc1 = fma2(acc1, wst[p * 128 + 32], h);
            acc2 = fma2(acc2, wst[p * 128 + 64], h);
            acc3 = fma2(acc3, wst[p * 128 + 96], h);
        }

        float a0x, a0y, a1x, a1y, a2x, a2y, a3x, a3y;
        unpack2(acc0, a0x, a0y);
        unpack2(acc1, a1x, a1y);
        unpack2(acc2, a2x, a2y);
        unpack2(acc3, a3x, a3y);
        S->red[w][0][l] = a0x + a0y;
        S->red[w][1][l] = a1x + a1y;
        S->red[w][2][l] = a2x + a2y;
        S->red[w][3][l] = a3x + a3y;
        __syncthreads();

        if (w == 0) {
            float gsum[4];
            #pragma unroll
            for (int q = 0; q < 4; q++) {
                float s = S->xg_s[q][l];
                #pragma unroll
                for (int kh = 0; kh < 8; kh++) s += S->red[kh][q][l];
                gsum[q] = s;
            }
            c_state = sigf(gsum[2] + 1.f) * c_state + sigf(gsum[0]) * tanh_f(gsum[1]);
            float h = sigf(gsum[3]) * tanh_f(c_state);
            unsigned hbits = __float_as_uint(h);

            const unsigned dst_off = hs_off + (unsigned)((((t + 1) & 1) * H_ + j) * 4);
            const unsigned mbr_off = mb_off + (unsigned)((t & 1) * 8);
            #pragma unroll
            for (int d = 0; d < 8; d++) {
                asm volatile(
                    "st.async.weak.shared::cluster.mbarrier::complete_tx::bytes.u32 [%0], %1, [%2];"
                    :: "r"(rbase[d] + dst_off), "r"(hbits), "r"(rbase[d] + mbr_off)
                    : "memory");
            }
            if (l == 0) {
                asm volatile("mbarrier.arrive.expect_tx.shared.b64 _, [%0], 1024;"
                             :: "r"(sbase + mbr_off) : "memory");
            }
            if (t == T_ - 1) g_h[g * H_ + j] = h;
        }
    }
    // drain final phase so no CTA exits with peer traffic in flight
    mbar_wait_cluster(sbase + mb_off + ((T_ - 1) & 1) * 8, ((T_ - 1) >> 1) & 1);
}

// ---------------- kernel 3: out = (h @ Wfc + bfc) @ Wout + bout ----------------
__global__ void __launch_bounds__(256) k_fc(const float* __restrict__ Wfc,
                                            const float* __restrict__ bfc,
                                            const float* __restrict__ Wout,
                                            const float* __restrict__ bout,
                                            float* __restrict__ out) {
    __shared__ float tmp[H_];
    int b = blockIdx.x;
    int jj = threadIdx.x;
    const float* h = &g_h[b * H_];
    float s = bfc[jj];
    #pragma unroll 8
    for (int k = 0; k < H_; k++) s += h[k] * Wfc[(size_t)k * H_ + jj];
    tmp[jj] = s;
    __syncthreads();
    if (jj < HOR_) {
        float o = bout[jj];
        #pragma unroll 8
        for (int k = 0; k < H_; k++) o += tmp[k] * Wout[(size_t)k * HOR_ + jj];
        out[b * HOR_ + jj] = o;
    }
}

// ---------------- launch ----------------
extern "C" void kernel_launch(void* const* d_in, const int* in_sizes, int n_in,
                              void* d_out, int out_size) {
    const float* x      = (const float*)d_in[0];
    const float* W_lstm = (const float*)d_in[1];
    const float* b_lstm = (const float*)d_in[2];
    const float* W_fc   = (const float*)d_in[3];
    const float* b_fc   = (const float*)d_in[4];
    const float* W_out  = (const float*)d_in[5];
    const float* b_out  = (const float*)d_in[6];
    float* out = (float*)d_out;

    cudaFuncSetAttribute(k_rnn, cudaFuncAttributeMaxDynamicSharedMemorySize,
                         (int)sizeof(RnnSmem));

    k_xgemm<<<dim3((B_ * T_) / MT, G4_ / NT), 256>>>(x, W_lstm, b_lstm);
    k_rnn<<<256, 256, sizeof(RnnSmem)>>>(W_lstm);
    k_fc<<<B_, 256>>>(W_fc, b_fc, W_out, b_out, out);
}